// round 2
// baseline (speedup 1.0000x reference)
#include <cuda_runtime.h>
#include <cstdint>

// ---------------------------------------------------------------------------
// Fused causal attention head via warp-level tf32 mma.sync (sm_103 non-'a'
// toolchain: tcgen05 unavailable). One CTA per batch element.
//   x:[4096,128,64] f32, Wq/Wk/Wv:[64,64] f32, out:[4096,128,64] f32
// 8 warps; warp w owns rows 16w..16w+15. Softmax in registers via quad
// shuffles. Causal tile skipping on S and PV.
// ---------------------------------------------------------------------------

#define DEVINL __device__ __forceinline__

static constexpr int T = 128;
static constexpr int C = 64;
static constexpr int H = 64;

// SMEM strides in floats, chosen for conflict-free fragment loads:
//  row-indexed frag loads (addr = r*stride + k) want stride % 32 == 4
//  col-indexed frag loads (addr = k*stride + n) want stride % 32 == 8
static constexpr int WST  = 68;   // W   (B-frag, row-indexed by n)
static constexpr int QKST = 68;   // Q/K (A-frag / B-frag, row-indexed)
static constexpr int VST  = 72;   // V   (B-frag, col-indexed by k)
static constexpr int PST  = 132;  // P   (A-frag, row-indexed)

static constexpr uint32_t WSZ  = 64 * WST * 4;            // 17408 per matrix
static constexpr uint32_t SM_W = 0;                       // 3 * 17408 = 52224
static constexpr uint32_t SM_Q = 3 * WSZ;                 // 52224
static constexpr uint32_t SM_K = SM_Q + 128 * QKST * 4;   // 87040
static constexpr uint32_t SM_V = SM_K + 128 * QKST * 4;   // 121856
static constexpr uint32_t SM_P = 0;                       // aliases W+Q (67584 <= 87040)
static constexpr uint32_t SM_TOT = SM_V + 128 * VST * 4;  // 158720

DEVINL uint32_t f2tf(float f) {
    uint32_t r; asm("cvt.rna.tf32.f32 %0, %1;" : "=r"(r) : "f"(f)); return r;
}
DEVINL float ex2f(float x) {
    float y; asm("ex2.approx.ftz.f32 %0, %1;" : "=f"(y) : "f"(x)); return y;
}

// D += A(16x8) * B(8x8), tf32, fp32 accum
DEVINL void mma8(float d[4], const uint32_t a[4], uint32_t b0, uint32_t b1) {
    asm volatile(
        "mma.sync.aligned.m16n8k8.row.col.f32.tf32.tf32.f32 "
        "{%0,%1,%2,%3}, {%4,%5,%6,%7}, {%8,%9}, {%0,%1,%2,%3};"
        : "+f"(d[0]), "+f"(d[1]), "+f"(d[2]), "+f"(d[3])
        : "r"(a[0]), "r"(a[1]), "r"(a[2]), "r"(a[3]), "r"(b0), "r"(b1));
}

extern "C" __global__ void __launch_bounds__(256, 1)
attn_head_kernel(const float* __restrict__ xg, const float* __restrict__ wqg,
                 const float* __restrict__ wkg, const float* __restrict__ wvg,
                 float* __restrict__ outg)
{
    extern __shared__ __align__(16) char sm[];
    const int tid  = threadIdx.x;
    const int lane = tid & 31;
    const int w    = tid >> 5;          // warp 0..7
    const int b    = blockIdx.x;
    const int g    = lane >> 2;         // group id 0..7
    const int q4   = lane & 3;          // thread-in-group
    const int r_lo = 16 * w + g;        // CTA-local rows owned by this lane
    const int r_hi = r_lo + 8;

    // ---- Stage W (tf32, Wq pre-scaled by 1/sqrt(64)) into SMEM ----
    for (int i = tid; i < 3 * 64 * 16; i += 256) {   // 12 float4s per thread
        int m = i >> 10, rem = i & 1023, h = rem >> 4, c4 = rem & 15;
        const float* wsrc = (m == 0) ? wqg : ((m == 1) ? wkg : wvg);
        float4 v = reinterpret_cast<const float4*>(wsrc)[h * 16 + c4];
        float sc = (m == 0) ? 0.125f : 1.0f;
        uint32_t* dst = reinterpret_cast<uint32_t*>(sm + SM_W + m * WSZ + (h * WST + c4 * 4) * 4);
        dst[0] = f2tf(v.x * sc); dst[1] = f2tf(v.y * sc);
        dst[2] = f2tf(v.z * sc); dst[3] = f2tf(v.w * sc);
    }

    // ---- X rows -> A-fragments straight from gmem ----
    const float* xb = xg + (size_t)b * T * C;
    uint32_t ax[8][4];
    #pragma unroll
    for (int kt = 0; kt < 8; kt++) {
        ax[kt][0] = f2tf(xb[r_lo * 64 + kt * 8 + q4]);
        ax[kt][1] = f2tf(xb[r_hi * 64 + kt * 8 + q4]);
        ax[kt][2] = f2tf(xb[r_lo * 64 + kt * 8 + q4 + 4]);
        ax[kt][3] = f2tf(xb[r_hi * 64 + kt * 8 + q4 + 4]);
    }
    __syncthreads();

    // ---- Phase 1: Q/K/V = X * W^T  (each warp: its 16 rows) ----
    #pragma unroll
    for (int m = 0; m < 3; m++) {
        const uint32_t wbase = SM_W + m * WSZ;
        const uint32_t obase = (m == 0) ? SM_Q : ((m == 1) ? SM_K : SM_V);
        const int ost = (m == 2) ? VST : QKST;
        #pragma unroll
        for (int nt = 0; nt < 8; nt++) {
            float acc[4] = {0.f, 0.f, 0.f, 0.f};
            #pragma unroll
            for (int kt = 0; kt < 8; kt++) {
                uint32_t a_ = wbase + ((nt * 8 + g) * WST + kt * 8 + q4) * 4;
                uint32_t b0 = *reinterpret_cast<const uint32_t*>(sm + a_);
                uint32_t b1 = *reinterpret_cast<const uint32_t*>(sm + a_ + 16);
                mma8(acc, ax[kt], b0, b1);
            }
            uint32_t* d0 = reinterpret_cast<uint32_t*>(sm + obase + (r_lo * ost + nt * 8 + 2 * q4) * 4);
            d0[0] = f2tf(acc[0]); d0[1] = f2tf(acc[1]);
            uint32_t* d1 = reinterpret_cast<uint32_t*>(sm + obase + (r_hi * ost + nt * 8 + 2 * q4) * 4);
            d1[0] = f2tf(acc[2]); d1[1] = f2tf(acc[3]);
        }
    }
    __syncthreads();

    // ---- Phase 2: S = Q * K^T (causal: skip fully-masked n-tiles) ----
    uint32_t aq[8][4];
    #pragma unroll
    for (int kt = 0; kt < 8; kt++) {
        aq[kt][0] = *reinterpret_cast<const uint32_t*>(sm + SM_Q + (r_lo * QKST + kt * 8 + q4) * 4);
        aq[kt][1] = *reinterpret_cast<const uint32_t*>(sm + SM_Q + (r_hi * QKST + kt * 8 + q4) * 4);
        aq[kt][2] = *reinterpret_cast<const uint32_t*>(sm + SM_Q + (r_lo * QKST + kt * 8 + q4 + 4) * 4);
        aq[kt][3] = *reinterpret_cast<const uint32_t*>(sm + SM_Q + (r_hi * QKST + kt * 8 + q4 + 4) * 4);
    }
    float s[16][4];
    #pragma unroll
    for (int nt = 0; nt < 16; nt++)
        s[nt][0] = s[nt][1] = s[nt][2] = s[nt][3] = 0.f;
    const int tile_max = 2 * w + 2;   // tiles [0, tile_max) touch the causal region
    #pragma unroll
    for (int nt = 0; nt < 16; nt++) {
        if (nt < tile_max) {
            #pragma unroll
            for (int kt = 0; kt < 8; kt++) {
                uint32_t a_ = SM_K + ((nt * 8 + g) * QKST + kt * 8 + q4) * 4;
                uint32_t b0 = *reinterpret_cast<const uint32_t*>(sm + a_);
                uint32_t b1 = *reinterpret_cast<const uint32_t*>(sm + a_ + 16);
                mma8(s[nt], aq[kt], b0, b1);
            }
        }
    }

    // ---- Causal softmax in registers (row spread over a lane quad) ----
    float m_lo = -1e30f, m_hi = -1e30f;
    #pragma unroll
    for (int nt = 0; nt < 16; nt++) {
        #pragma unroll
        for (int e = 0; e < 2; e++) {
            int col = nt * 8 + 2 * q4 + e;
            if (col <= r_lo) m_lo = fmaxf(m_lo, s[nt][e]);
            if (col <= r_hi) m_hi = fmaxf(m_hi, s[nt][2 + e]);
        }
    }
    m_lo = fmaxf(m_lo, __shfl_xor_sync(~0u, m_lo, 1));
    m_lo = fmaxf(m_lo, __shfl_xor_sync(~0u, m_lo, 2));
    m_hi = fmaxf(m_hi, __shfl_xor_sync(~0u, m_hi, 1));
    m_hi = fmaxf(m_hi, __shfl_xor_sync(~0u, m_hi, 2));

    const float L2E = 1.4426950408889634f;
    float sum_lo = 0.f, sum_hi = 0.f;
    #pragma unroll
    for (int nt = 0; nt < 16; nt++) {
        #pragma unroll
        for (int e = 0; e < 2; e++) {
            int col = nt * 8 + 2 * q4 + e;
            float pl = (col <= r_lo) ? ex2f((s[nt][e]     - m_lo) * L2E) : 0.f;
            float ph = (col <= r_hi) ? ex2f((s[nt][2 + e] - m_hi) * L2E) : 0.f;
            sum_lo += pl; sum_hi += ph;
            s[nt][e]     = __uint_as_float(f2tf(pl));   // reuse regs: P (tf32 bits)
            s[nt][2 + e] = __uint_as_float(f2tf(ph));
        }
    }
    sum_lo += __shfl_xor_sync(~0u, sum_lo, 1);
    sum_lo += __shfl_xor_sync(~0u, sum_lo, 2);
    sum_hi += __shfl_xor_sync(~0u, sum_hi, 1);
    sum_hi += __shfl_xor_sync(~0u, sum_hi, 2);
    const float inv_lo = 1.f / sum_lo, inv_hi = 1.f / sum_hi;

    __syncthreads();   // all warps finished reading Q/K/W before P overwrites them

    #pragma unroll
    for (int nt = 0; nt < 16; nt++) {
        uint32_t* d0 = reinterpret_cast<uint32_t*>(sm + SM_P + (r_lo * PST + nt * 8 + 2 * q4) * 4);
        d0[0] = __float_as_uint(s[nt][0]); d0[1] = __float_as_uint(s[nt][1]);
        uint32_t* d1 = reinterpret_cast<uint32_t*>(sm + SM_P + (r_hi * PST + nt * 8 + 2 * q4) * 4);
        d1[0] = __float_as_uint(s[nt][2]); d1[1] = __float_as_uint(s[nt][3]);
    }
    __syncthreads();

    // ---- Phase 4: O = P * V (causal: skip zero k-tiles) ----
    float o[8][4];
    #pragma unroll
    for (int nt = 0; nt < 8; nt++)
        o[nt][0] = o[nt][1] = o[nt][2] = o[nt][3] = 0.f;
    #pragma unroll
    for (int kt = 0; kt < 16; kt++) {
        if (kt < tile_max) {
            uint32_t ap[4];
            ap[0] = *reinterpret_cast<const uint32_t*>(sm + SM_P + (r_lo * PST + kt * 8 + q4) * 4);
            ap[1] = *reinterpret_cast<const uint32_t*>(sm + SM_P + (r_hi * PST + kt * 8 + q4) * 4);
            ap[2] = *reinterpret_cast<const uint32_t*>(sm + SM_P + (r_lo * PST + kt * 8 + q4 + 4) * 4);
            ap[3] = *reinterpret_cast<const uint32_t*>(sm + SM_P + (r_hi * PST + kt * 8 + q4 + 4) * 4);
            #pragma unroll
            for (int nt = 0; nt < 8; nt++) {
                uint32_t a_ = SM_V + ((kt * 8 + q4) * VST + nt * 8 + g) * 4;
                uint32_t b0 = *reinterpret_cast<const uint32_t*>(sm + a_);
                uint32_t b1 = *reinterpret_cast<const uint32_t*>(sm + a_ + 4 * VST * 4);
                mma8(o[nt], ap, b0, b1);
            }
        }
    }

    // ---- Normalize and store ----
    float* ob = outg + (size_t)b * T * H;
    #pragma unroll
    for (int nt = 0; nt < 8; nt++) {
        float2 vlo = make_float2(o[nt][0] * inv_lo, o[nt][1] * inv_lo);
        float2 vhi = make_float2(o[nt][2] * inv_hi, o[nt][3] * inv_hi);
        *reinterpret_cast<float2*>(ob + r_lo * 64 + nt * 8 + 2 * q4) = vlo;
        *reinterpret_cast<float2*>(ob + r_hi * 64 + nt * 8 + 2 * q4) = vhi;
    }
}

// ------------------------------ launcher -----------------------------------

extern "C" void kernel_launch(void* const* d_in, const int* in_sizes, int n_in,
                              void* d_out, int out_size) {
    const float* x  = (const float*)d_in[0];
    const float* wq = (const float*)d_in[1];
    const float* wk = (const float*)d_in[2];
    const float* wv = (const float*)d_in[3];
    float* out = (float*)d_out;
    const int nb = in_sizes[0] / (T * C);

    cudaFuncSetAttribute(attn_head_kernel,
                         cudaFuncAttributeMaxDynamicSharedMemorySize, (int)SM_TOT);
    attn_head_kernel<<<nb, 256, SM_TOT>>>(x, wq, wk, wv, out);
}

// round 3
// speedup vs baseline: 1.7256x; 1.7256x over previous
#include <cuda_runtime.h>
#include <cstdint>

// ---------------------------------------------------------------------------
// Fused causal attention head via warp-level tf32 mma.sync. One CTA per batch,
// 2 CTAs/SM. Q and P live entirely in registers (accum->A-frag via quad
// shuffles); only W-staging / K / V use SMEM (104 KB).
//   x:[4096,128,64] f32, Wq/Wk/Wv:[64,64] f32, out:[4096,128,64] f32
// ---------------------------------------------------------------------------

#define DEVINL __device__ __forceinline__

static constexpr int T = 128;
static constexpr int C = 64;
static constexpr int H = 64;

// SMEM strides in floats (bank-conflict-free fragment access):
//  row-indexed frag loads (addr = r*stride + k) want stride % 32 == 4
//  col-indexed frag loads (addr = k*stride + n) want stride % 32 == 8
static constexpr int WST  = 68;   // staged W (B-frag, row-indexed)
static constexpr int KST  = 68;   // K (B-frag, row-indexed)
static constexpr int VST  = 72;   // V (B-frag, col-indexed)

static constexpr uint32_t WSZ    = 64 * WST * 4;          // 17408 per matrix
static constexpr uint32_t SM_W   = 0;                     // Wk@0, Wv@17408; later Wq@0
static constexpr uint32_t SM_K   = 2 * WSZ;               // 34816
static constexpr uint32_t SM_V   = SM_K + 128 * KST * 4;  // 69632
static constexpr uint32_t SM_TOT = SM_V + 128 * VST * 4;  // 106496 -> 2 CTAs/SM

DEVINL uint32_t f2tf(float f) {
    uint32_t r; asm("cvt.rna.tf32.f32 %0, %1;" : "=r"(r) : "f"(f)); return r;
}
DEVINL float ex2f(float x) {
    float y; asm("ex2.approx.ftz.f32 %0, %1;" : "=f"(y) : "f"(x)); return y;
}

// D += A(16x8) * B(8x8), tf32, fp32 accum
DEVINL void mma8(float d[4], const uint32_t a[4], uint32_t b0, uint32_t b1) {
    asm volatile(
        "mma.sync.aligned.m16n8k8.row.col.f32.tf32.tf32.f32 "
        "{%0,%1,%2,%3}, {%4,%5,%6,%7}, {%8,%9}, {%0,%1,%2,%3};"
        : "+f"(d[0]), "+f"(d[1]), "+f"(d[2]), "+f"(d[3])
        : "r"(a[0]), "r"(a[1]), "r"(a[2]), "r"(a[3]), "r"(b0), "r"(b1));
}

extern "C" __global__ void __launch_bounds__(256, 2)
attn_head_kernel(const float* __restrict__ xg, const float* __restrict__ wqg,
                 const float* __restrict__ wkg, const float* __restrict__ wvg,
                 float* __restrict__ outg)
{
    extern __shared__ __align__(16) char sm[];
    const int tid  = threadIdx.x;
    const int lane = tid & 31;
    const int w    = tid >> 5;          // warp 0..7
    const int b    = blockIdx.x;
    const int g    = lane >> 2;         // group id 0..7
    const int q4   = lane & 3;          // thread-in-group 0..3
    const int r_lo = 16 * w + g;        // CTA-local rows owned by this lane
    const int r_hi = r_lo + 8;
    const bool odd = (q4 & 1);
    const int half = q4 >> 1;

    // ---- Prefetch Wq into registers (staged to SMEM later, after K/V) ----
    float4 wqv[4];
    #pragma unroll
    for (int j = 0; j < 4; j++)
        wqv[j] = reinterpret_cast<const float4*>(wqg)[tid + j * 256];

    // ---- Stage Wk, Wv (tf32) ----
    #pragma unroll
    for (int m = 0; m < 2; m++) {
        const float* wsrc = (m == 0) ? wkg : wvg;
        #pragma unroll
        for (int j = 0; j < 4; j++) {
            int i = tid + j * 256;          // 0..1023 float4
            int h = i >> 4, c4 = i & 15;
            float4 v = reinterpret_cast<const float4*>(wsrc)[i];
            uint32_t* dst = reinterpret_cast<uint32_t*>(sm + SM_W + m * WSZ + (h * WST + c4 * 4) * 4);
            dst[0] = f2tf(v.x); dst[1] = f2tf(v.y); dst[2] = f2tf(v.z); dst[3] = f2tf(v.w);
        }
    }

    // ---- X rows -> A-fragments straight from gmem ----
    const float* xb = xg + (size_t)b * T * C;
    uint32_t ax[8][4];
    #pragma unroll
    for (int kt = 0; kt < 8; kt++) {
        ax[kt][0] = f2tf(xb[r_lo * 64 + kt * 8 + q4]);
        ax[kt][1] = f2tf(xb[r_hi * 64 + kt * 8 + q4]);
        ax[kt][2] = f2tf(xb[r_lo * 64 + kt * 8 + q4 + 4]);
        ax[kt][3] = f2tf(xb[r_hi * 64 + kt * 8 + q4 + 4]);
    }
    __syncthreads();

    // ---- Phase 1a: K = X*Wk^T -> SMEM, V = X*Wv^T -> SMEM ----
    #pragma unroll
    for (int m = 0; m < 2; m++) {
        const uint32_t wbase = SM_W + m * WSZ;
        const uint32_t obase = (m == 0) ? SM_K : SM_V;
        const int ost = (m == 0) ? KST : VST;
        #pragma unroll
        for (int nt = 0; nt < 8; nt++) {
            float acc[4] = {0.f, 0.f, 0.f, 0.f};
            #pragma unroll
            for (int kt = 0; kt < 8; kt++) {
                uint32_t a_ = wbase + ((nt * 8 + g) * WST + kt * 8 + q4) * 4;
                uint32_t b0 = *reinterpret_cast<const uint32_t*>(sm + a_);
                uint32_t b1 = *reinterpret_cast<const uint32_t*>(sm + a_ + 16);
                mma8(acc, ax[kt], b0, b1);
            }
            uint32_t* d0 = reinterpret_cast<uint32_t*>(sm + obase + (r_lo * ost + nt * 8 + 2 * q4) * 4);
            d0[0] = f2tf(acc[0]); d0[1] = f2tf(acc[1]);
            uint32_t* d1 = reinterpret_cast<uint32_t*>(sm + obase + (r_hi * ost + nt * 8 + 2 * q4) * 4);
            d1[0] = f2tf(acc[2]); d1[1] = f2tf(acc[3]);
        }
    }
    __syncthreads();   // K/V done; Wk region free

    // ---- Phase 1b: stage Wq (pre-scaled by 1/sqrt(64)) over Wk region ----
    #pragma unroll
    for (int j = 0; j < 4; j++) {
        int i = tid + j * 256;
        int h = i >> 4, c4 = i & 15;
        float4 v = wqv[j];
        uint32_t* dst = reinterpret_cast<uint32_t*>(sm + SM_W + (h * WST + c4 * 4) * 4);
        dst[0] = f2tf(v.x * 0.125f); dst[1] = f2tf(v.y * 0.125f);
        dst[2] = f2tf(v.z * 0.125f); dst[3] = f2tf(v.w * 0.125f);
    }
    __syncthreads();

    // ---- Phase 1c: Q = X*Wq^T -> registers (accumulator layout) ----
    float q[8][4];
    #pragma unroll
    for (int nt = 0; nt < 8; nt++) {
        q[nt][0] = q[nt][1] = q[nt][2] = q[nt][3] = 0.f;
        #pragma unroll
        for (int kt = 0; kt < 8; kt++) {
            uint32_t a_ = SM_W + ((nt * 8 + g) * WST + kt * 8 + q4) * 4;
            uint32_t b0 = *reinterpret_cast<const uint32_t*>(sm + a_);
            uint32_t b1 = *reinterpret_cast<const uint32_t*>(sm + a_ + 16);
            mma8(q[nt], ax[kt], b0, b1);
        }
    }

    // ---- Accum layout -> A-fragment layout via quad shuffles (one-time) ----
    // a0 = Q[r_lo][kt*8+q4], a1 = Q[r_hi][..], a2/a3 = same +4 cols.
    uint32_t aq[8][4];
    #pragma unroll
    for (int kt = 0; kt < 8; kt++) {
        float t0 = __shfl_sync(~0u, q[kt][0], half, 4);
        float t1 = __shfl_sync(~0u, q[kt][1], half, 4);
        float t2 = __shfl_sync(~0u, q[kt][2], half, 4);
        float t3 = __shfl_sync(~0u, q[kt][3], half, 4);
        float u0 = __shfl_sync(~0u, q[kt][0], half + 2, 4);
        float u1 = __shfl_sync(~0u, q[kt][1], half + 2, 4);
        float u2 = __shfl_sync(~0u, q[kt][2], half + 2, 4);
        float u3 = __shfl_sync(~0u, q[kt][3], half + 2, 4);
        aq[kt][0] = f2tf(odd ? t1 : t0);
        aq[kt][1] = f2tf(odd ? t3 : t2);
        aq[kt][2] = f2tf(odd ? u1 : u0);
        aq[kt][3] = f2tf(odd ? u3 : u2);
    }

    // ---- Phase 2: S = Q * K^T (causal: skip fully-masked n-tiles) ----
    float s[16][4];
    #pragma unroll
    for (int nt = 0; nt < 16; nt++)
        s[nt][0] = s[nt][1] = s[nt][2] = s[nt][3] = 0.f;
    const int tile_max = 2 * w + 2;     // tiles [0, tile_max) touch causal region
    #pragma unroll
    for (int nt = 0; nt < 16; nt++) {
        if (nt < tile_max) {
            #pragma unroll
            for (int kt = 0; kt < 8; kt++) {
                uint32_t a_ = SM_K + ((nt * 8 + g) * KST + kt * 8 + q4) * 4;
                uint32_t b0 = *reinterpret_cast<const uint32_t*>(sm + a_);
                uint32_t b1 = *reinterpret_cast<const uint32_t*>(sm + a_ + 16);
                mma8(s[nt], aq[kt], b0, b1);
            }
        }
    }

    // ---- Causal softmax in registers (row spread over a lane quad) ----
    float m_lo = -1e30f, m_hi = -1e30f;
    #pragma unroll
    for (int nt = 0; nt < 16; nt++) {
        #pragma unroll
        for (int e = 0; e < 2; e++) {
            int col = nt * 8 + 2 * q4 + e;
            if (col <= r_lo) m_lo = fmaxf(m_lo, s[nt][e]);
            if (col <= r_hi) m_hi = fmaxf(m_hi, s[nt][2 + e]);
        }
    }
    m_lo = fmaxf(m_lo, __shfl_xor_sync(~0u, m_lo, 1));
    m_lo = fmaxf(m_lo, __shfl_xor_sync(~0u, m_lo, 2));
    m_hi = fmaxf(m_hi, __shfl_xor_sync(~0u, m_hi, 1));
    m_hi = fmaxf(m_hi, __shfl_xor_sync(~0u, m_hi, 2));

    const float L2E = 1.4426950408889634f;
    float sum_lo = 0.f, sum_hi = 0.f;
    #pragma unroll
    for (int nt = 0; nt < 16; nt++) {
        #pragma unroll
        for (int e = 0; e < 2; e++) {
            int col = nt * 8 + 2 * q4 + e;
            float pl = (col <= r_lo) ? ex2f((s[nt][e]     - m_lo) * L2E) : 0.f;
            float ph = (col <= r_hi) ? ex2f((s[nt][2 + e] - m_hi) * L2E) : 0.f;
            sum_lo += pl; sum_hi += ph;
            s[nt][e]     = __uint_as_float(f2tf(pl));   // P, tf32 bits, accum layout
            s[nt][2 + e] = __uint_as_float(f2tf(ph));
        }
    }
    sum_lo += __shfl_xor_sync(~0u, sum_lo, 1);
    sum_lo += __shfl_xor_sync(~0u, sum_lo, 2);
    sum_hi += __shfl_xor_sync(~0u, sum_hi, 1);
    sum_hi += __shfl_xor_sync(~0u, sum_hi, 2);
    const float inv_lo = 1.f / sum_lo, inv_hi = 1.f / sum_hi;

    // ---- Phase 4: O = P * V (P converted to A-frags on the fly; no SMEM) ----
    float o[8][4];
    #pragma unroll
    for (int nt = 0; nt < 8; nt++)
        o[nt][0] = o[nt][1] = o[nt][2] = o[nt][3] = 0.f;
    #pragma unroll
    for (int kt = 0; kt < 16; kt++) {
        if (kt < tile_max) {
            float t0 = __shfl_sync(~0u, s[kt][0], half, 4);
            float t1 = __shfl_sync(~0u, s[kt][1], half, 4);
            float t2 = __shfl_sync(~0u, s[kt][2], half, 4);
            float t3 = __shfl_sync(~0u, s[kt][3], half, 4);
            float u0 = __shfl_sync(~0u, s[kt][0], half + 2, 4);
            float u1 = __shfl_sync(~0u, s[kt][1], half + 2, 4);
            float u2 = __shfl_sync(~0u, s[kt][2], half + 2, 4);
            float u3 = __shfl_sync(~0u, s[kt][3], half + 2, 4);
            uint32_t ap[4];
            ap[0] = __float_as_uint(odd ? t1 : t0);
            ap[1] = __float_as_uint(odd ? t3 : t2);
            ap[2] = __float_as_uint(odd ? u1 : u0);
            ap[3] = __float_as_uint(odd ? u3 : u2);
            #pragma unroll
            for (int nt = 0; nt < 8; nt++) {
                uint32_t a_ = SM_V + ((kt * 8 + q4) * VST + nt * 8 + g) * 4;
                uint32_t b0 = *reinterpret_cast<const uint32_t*>(sm + a_);
                uint32_t b1 = *reinterpret_cast<const uint32_t*>(sm + a_ + 4 * VST * 4);
                mma8(o[nt], ap, b0, b1);
            }
        }
    }

    // ---- Normalize and store ----
    float* ob = outg + (size_t)b * T * H;
    #pragma unroll
    for (int nt = 0; nt < 8; nt++) {
        float2 vlo = make_float2(o[nt][0] * inv_lo, o[nt][1] * inv_lo);
        float2 vhi = make_float2(o[nt][2] * inv_hi, o[nt][3] * inv_hi);
        *reinterpret_cast<float2*>(ob + r_lo * 64 + nt * 8 + 2 * q4) = vlo;
        *reinterpret_cast<float2*>(ob + r_hi * 64 + nt * 8 + 2 * q4) = vhi;
    }
}

// ------------------------------ launcher -----------------------------------

extern "C" void kernel_launch(void* const* d_in, const int* in_sizes, int n_in,
                              void* d_out, int out_size) {
    const float* x  = (const float*)d_in[0];
    const float* wq = (const float*)d_in[1];
    const float* wk = (const float*)d_in[2];
    const float* wv = (const float*)d_in[3];
    float* out = (float*)d_out;
    const int nb = in_sizes[0] / (T * C);

    cudaFuncSetAttribute(attn_head_kernel,
                         cudaFuncAttributeMaxDynamicSharedMemorySize, (int)SM_TOT);
    attn_head_kernel<<<nb, 256, SM_TOT>>>(x, wq, wk, wv, out);
}